// round 11
// baseline (speedup 1.0000x reference)
#include <cuda_runtime.h>
#include <cstdint>
#include <float.h>

// Problem constants
#define N_ROWS 16384   // 16*32*32
#define DIM    256
#define NEMB   2048
#define KTOP   4

// GEMM tiling
#define BM 128
#define BN 128
#define BKD 16
#define TM 8
#define TN 8
#define NTHREADS 256
#define NBLOCKS (N_ROWS / BM)   // 128
#define OUTBLOCKS 256

// Scratch (no cudaMalloc allowed)
__device__ float g_codeT[NEMB * DIM];    // codebook row-major: [code][dim]
__device__ float g_enorm[NEMB];          // ||e_c||^2 (set-A emitter emulation)
__device__ float g_xnorm[N_ROWS];        // ||x_r||^2 (flip-inert, 3 paired tests)
__device__ int   g_top[N_ROWS * KTOP];   // top-4 indices (topk-kernel tie policy)
__device__ float g_key2[N_ROWS * 2];     // top-2 keys (for argmax low-first policy)
__device__ double g_partial[OUTBLOCKS];  // per-block diff partial sums

// ---------------------------------------------------------------------------
// Kernel 1: transpose embed [DIM][NEMB] -> g_codeT [NEMB][DIM]
// ---------------------------------------------------------------------------
__global__ void k_transpose(const float* __restrict__ embed) {
    __shared__ float t[32][33];
    int c = blockIdx.x * 32 + threadIdx.x;
#pragma unroll
    for (int j = 0; j < 4; j++) {
        int d = blockIdx.y * 32 + threadIdx.y + j * 8;
        t[threadIdx.y + j * 8][threadIdx.x] = embed[d * NEMB + c];
    }
    __syncthreads();
    int d = blockIdx.y * 32 + threadIdx.x;
#pragma unroll
    for (int j = 0; j < 4; j++) {
        int c2 = blockIdx.x * 32 + threadIdx.y + j * 8;
        g_codeT[c2 * DIM + d] = t[threadIdx.x][threadIdx.y + j * 8];
    }
}

// ---------------------------------------------------------------------------
// Kernel 2: code norms ||e_c||^2 — set-A emitter (best correlate): 32x32 tile,
// per-thread partial over 8 rows at stride 32 (fma-contracted), smem transpose
// + 32-lane halving tree of plain fadds.
// ---------------------------------------------------------------------------
__global__ void k_enorm(const float* __restrict__ embed) {
    __shared__ float p[32][33];
    int c  = blockIdx.x * 32 + threadIdx.x;   // code (coalesced across tx)
    int ty = threadIdx.y;                     // row-lane 0..31
    float s = 0.f;
#pragma unroll
    for (int i = 0; i < DIM / 32; i++) {
        float v = embed[(size_t)(ty + 32 * i) * NEMB + c];
        s = __fmaf_rn(v, v, s);
    }
    p[ty][threadIdx.x] = s;
    __syncthreads();
#pragma unroll
    for (int step = 16; step > 0; step >>= 1) {
        if (ty < step) p[ty][threadIdx.x] = __fadd_rn(p[ty][threadIdx.x], p[ty + step][threadIdx.x]);
        __syncthreads();
    }
    if (ty == 0) g_enorm[c] = p[0][threadIdx.x];
}

// ---------------------------------------------------------------------------
// Kernel 3: row norms ||x_r||^2 (flip-inert)
// ---------------------------------------------------------------------------
__global__ void k_xnorm(const float* __restrict__ input) {
    int row  = blockIdx.x * 8 + (threadIdx.x >> 5);
    int lane = threadIdx.x & 31;
    float s = 0.f;
#pragma unroll
    for (int i = 0; i < DIM / 32; i++) {
        float v = input[(size_t)row * DIM + lane + 32 * i];
        s = __fmaf_rn(v, v, s);
    }
#pragma unroll
    for (int o = 16; o; o >>= 1)
        s = __fadd_rn(s, __shfl_down_sync(0xffffffffu, s, o));
    if (lane == 0) g_xnorm[row] = s;
}

// ---------------------------------------------------------------------------
// Packed fp32x2 helpers (sm_103a)
// ---------------------------------------------------------------------------
__device__ __forceinline__ unsigned long long pack2(float a) {
    unsigned long long r;
    asm("mov.b64 %0, {%1, %1};" : "=l"(r) : "f"(a));
    return r;
}
__device__ __forceinline__ void fma2(unsigned long long& d,
                                     unsigned long long a,
                                     unsigned long long b) {
    asm("fma.rn.f32x2 %0, %1, %2, %0;" : "+l"(d) : "l"(a), "l"(b));
}

// TOP-K ORDER (hypothesis: XLA TopK custom kernel, unstable bitonic merge):
// smaller dist wins; EXACT TIE -> HIGHER index first.
__device__ __forceinline__ bool kbetter(float k1, int i1, float k2, int i2) {
    return (k1 < k2) || (k1 == k2 && i1 > i2);
}

// ---------------------------------------------------------------------------
// Kernel 4: fp32 distance GEMM (ascending-k fused FMA chain per element,
// = cublas fp32 SIMT sgemm) + per-row top-4 on emulated dist:
//   dist = fl( fl(||x||^2 - 2*dot) + ||e||^2 )
// ---------------------------------------------------------------------------
__global__ __launch_bounds__(NTHREADS, 1)
void k_main(const float* __restrict__ input, const float* __restrict__ embed) {
    __shared__ float As[BKD][BM + 4];
    __shared__ float Bs[BKD][BN];
    __shared__ float s_key[BM][KTOP];
    __shared__ int   s_idx[BM][KTOP];
    __shared__ int   s_lock[BM];
    __shared__ float s_en[BN];
    __shared__ float s_a[BM];

    const int tid  = threadIdx.x;
    const int rowg = tid >> 4;      // 0..15
    const int colg = tid & 15;      // 0..15
    const int row0 = blockIdx.x * BM;

    for (int r = tid; r < BM; r += NTHREADS) {
#pragma unroll
        for (int k = 0; k < KTOP; k++) { s_key[r][k] = FLT_MAX; s_idx[r][k] = 0x7fffffff; }
        s_lock[r] = 0;
        s_a[r] = g_xnorm[row0 + r];
    }
    __syncthreads();

    volatile float (*vkey)[KTOP] = (volatile float (*)[KTOP])s_key;
    volatile int   (*vidx)[KTOP] = (volatile int   (*)[KTOP])s_idx;

    for (int ct = 0; ct < NEMB / BN; ct++) {
        const int c0 = ct * BN;
        __syncthreads();
        if (tid < BN) s_en[tid] = g_enorm[c0 + tid];

        unsigned long long acc[TM][TN / 2];
#pragma unroll
        for (int i = 0; i < TM; i++)
#pragma unroll
            for (int j = 0; j < TN / 2; j++) acc[i][j] = 0ull;

        for (int kt = 0; kt < DIM / BKD; kt++) {
#pragma unroll
            for (int i = 0; i < (BM * BKD) / NTHREADS; i++) {
                int e  = tid + i * NTHREADS;
                int kk = e & (BKD - 1);
                int r  = e >> 4;
                As[kk][r] = input[(size_t)(row0 + r) * DIM + kt * BKD + kk];
            }
#pragma unroll
            for (int i = 0; i < (BN * BKD) / NTHREADS; i++) {
                int e  = tid + i * NTHREADS;
                int cc = e & (BN - 1);
                int kk = e >> 7;
                Bs[kk][cc] = embed[(size_t)(kt * BKD + kk) * NEMB + c0 + cc];
            }
            __syncthreads();
#pragma unroll
            for (int kk = 0; kk < BKD; kk++) {
                float4 a0 = *(const float4*)&As[kk][rowg * TM];
                float4 a1 = *(const float4*)&As[kk][rowg * TM + 4];
                ulonglong2 b0 = *(const ulonglong2*)&Bs[kk][colg * TN];
                ulonglong2 b1 = *(const ulonglong2*)&Bs[kk][colg * TN + 4];
                unsigned long long av[TM] = {pack2(a0.x), pack2(a0.y), pack2(a0.z), pack2(a0.w),
                                             pack2(a1.x), pack2(a1.y), pack2(a1.z), pack2(a1.w)};
                unsigned long long bv[4]  = {b0.x, b0.y, b1.x, b1.y};
#pragma unroll
                for (int i = 0; i < TM; i++)
#pragma unroll
                    for (int j = 0; j < 4; j++) fma2(acc[i][j], av[i], bv[j]);
            }
            __syncthreads();
        }

        // Epilogue: dist = fl(fl(xn - 2*dot) + en)
#pragma unroll
        for (int i = 0; i < TM; i++) {
            const int r = rowg * TM + i;
            const float a = s_a[r];
            float key[TN];
#pragma unroll
            for (int j = 0; j < 4; j++) {
                unsigned long long v = acc[i][j];
                float lo = __uint_as_float((unsigned)v);
                float hi = __uint_as_float((unsigned)(v >> 32));
                key[2 * j]     = __fadd_rn(__fsub_rn(a, __fmul_rn(2.0f, lo)),
                                           s_en[colg * TN + 2 * j]);
                key[2 * j + 1] = __fadd_rn(__fsub_rn(a, __fmul_rn(2.0f, hi)),
                                           s_en[colg * TN + 2 * j + 1]);
            }
            float rmin = key[0];
#pragma unroll
            for (int j = 1; j < TN; j++) rmin = fminf(rmin, key[j]);

            if (rmin <= vkey[r][KTOP - 1]) {          // rare path
                for (int j = 0; j < TN; j++) {
                    const int c = c0 + colg * TN + j;
                    const float kv = key[j];
                    float th = vkey[r][KTOP - 1];
                    int   ti = vidx[r][KTOP - 1];
                    if (kbetter(kv, c, th, ti)) {
                        while (atomicCAS(&s_lock[r], 0, 1) != 0) {}
                        __threadfence_block();
                        volatile float* rk = vkey[r];
                        volatile int*   ri = vidx[r];
                        if (kbetter(kv, c, rk[KTOP - 1], ri[KTOP - 1])) {
                            int p = KTOP - 1;
                            while (p > 0 && kbetter(kv, c, rk[p - 1], ri[p - 1])) {
                                rk[p] = rk[p - 1];
                                ri[p] = ri[p - 1];
                                p--;
                            }
                            rk[p] = kv;
                            ri[p] = c;
                        }
                        __threadfence_block();
                        atomicExch(&s_lock[r], 0);
                    }
                }
            }
        }
    }
    __syncthreads();

    for (int e = tid; e < BM * KTOP; e += NTHREADS) {
        int r = e >> 2;
        int k = e & 3;
        g_top[(size_t)(row0 + r) * KTOP + k] = s_idx[r][k];
    }
    // Export top-2 keys so the argmax path can apply LOW-index tie policy
    for (int r = tid; r < BM; r += NTHREADS) {
        g_key2[(size_t)(row0 + r) * 2 + 0] = s_key[r][0];
        g_key2[(size_t)(row0 + r) * 2 + 1] = s_key[r][1];
    }
}

// ---------------------------------------------------------------------------
// Kernel 5: outputs — top-k gather (topk policy), straight-through + diff
// (argmax policy: exact tie -> LOWER index)
// ---------------------------------------------------------------------------
__global__ __launch_bounds__(256)
void k_out(const float* __restrict__ input,
           float* __restrict__ out_topk, float* __restrict__ out_st) {
    const int tid = threadIdx.x;
    const int gsz = gridDim.x * blockDim.x;
    const int gid = blockIdx.x * blockDim.x + tid;

    for (long e = gid; e < (long)N_ROWS * KTOP * DIM; e += gsz) {
        int r = (int)(e >> 10);
        int k = (int)((e >> 8) & 3);
        int d = (int)(e & 255);
        int c = g_top[(size_t)r * KTOP + k];
        out_topk[e] = g_codeT[(size_t)c * DIM + d];
    }
    double part = 0.0;
    for (long e = gid; e < (long)N_ROWS * DIM; e += gsz) {
        int r = (int)(e >> 8);
        int d = (int)(e & 255);
        int i0 = g_top[(size_t)r * KTOP + 0];
        int i1 = g_top[(size_t)r * KTOP + 1];
        float k0 = g_key2[(size_t)r * 2 + 0];
        float k1 = g_key2[(size_t)r * 2 + 1];
        int c = (k0 == k1) ? min(i0, i1) : i0;   // argmax: low-index tie-break
        float q = g_codeT[(size_t)c * DIM + d];
        float x = input[e];
        out_st[e] = __fadd_rn(x, __fsub_rn(q, x));
        double dd = (double)q - (double)x;
        part += dd * dd;
    }
#pragma unroll
    for (int o = 16; o; o >>= 1) part += __shfl_xor_sync(0xffffffffu, part, o);
    __shared__ double s_red[8];
    if ((tid & 31) == 0) s_red[tid >> 5] = part;
    __syncthreads();
    if (tid == 0) {
        double t = 0.0;
#pragma unroll
        for (int i = 0; i < 8; i++) t += s_red[i];
        g_partial[blockIdx.x] = t;
    }
}

// ---------------------------------------------------------------------------
// Kernel 6: deterministic fixed-order diff reduction
// ---------------------------------------------------------------------------
__global__ void k_diff(float* __restrict__ out_diff) {
    if (threadIdx.x == 0) {
        double s = 0.0;
        for (int i = 0; i < OUTBLOCKS; i++) s += g_partial[i];
        out_diff[0] = (float)(s / (double)((long)N_ROWS * DIM));
    }
}

// ---------------------------------------------------------------------------
extern "C" void kernel_launch(void* const* d_in, const int* in_sizes, int n_in,
                              void* d_out, int out_size) {
    const float* input = (const float*)d_in[0];
    const float* embed = (const float*)d_in[1];
    if (n_in >= 2 && in_sizes[0] == NEMB * DIM && in_sizes[1] == N_ROWS * DIM) {
        input = (const float*)d_in[1];
        embed = (const float*)d_in[0];
    }
    float* out      = (float*)d_out;
    float* out_topk = out;                                  // 16384*1024
    float* out_diff = out + (size_t)N_ROWS * KTOP * DIM;    // 1
    float* out_st   = out_diff + 1;                         // 16384*256

    k_transpose<<<dim3(NEMB / 32, DIM / 32), dim3(32, 8)>>>(embed);
    k_enorm<<<NEMB / 32, dim3(32, 32)>>>(embed);
    k_xnorm<<<N_ROWS / 8, 256>>>(input);
    k_main<<<NBLOCKS, NTHREADS>>>(input, embed);
    k_out<<<OUTBLOCKS, 256>>>(input, out_topk, out_st);
    k_diff<<<1, 32>>>(out_diff);
}